// round 15
// baseline (speedup 1.0000x reference)
#include <cuda_runtime.h>
#include <cuda_fp16.h>
#include <cstdint>
#include <math.h>

#define NE   8
#define DD   1024
#define FF   4096
#define TMAX 4096

// ---------------- device scratch ----------------
__device__ int    g_cnt[NE];
__device__ int    g_tok[NE * TMAX];
__device__ float  g_wt [NE * TMAX];
__device__ __half g_Xh [(size_t)TMAX * DD];          // fp16 x (k-major)
__device__ __half g_w1t[(size_t)NE * DD * FF];       // fp16 w1^T : [E][F][D] (n-major)
__device__ __half g_w3t[(size_t)NE * DD * FF];       // fp16 w3^T : [E][F][D]
__device__ __half g_w2t[(size_t)NE * FF * DD];       // fp16 w2^T : [E][D][F]
__device__ __half g_H  [(size_t)NE * TMAX * FF];     // fp16 SwiGLU acts (k-major)

// ---------------- helpers ----------------
__device__ __forceinline__ uint32_t smem_u32(const void* p) {
    uint32_t a;
    asm("{ .reg .u64 t; cvta.to.shared.u64 t, %1; cvt.u32.u64 %0, t; }" : "=r"(a) : "l"(p));
    return a;
}
__device__ __forceinline__ void cp16(uint32_t dst, const void* src) {
    asm volatile("cp.async.cg.shared.global [%0], [%1], 16;" :: "r"(dst), "l"(src));
}
__device__ __forceinline__ void cp_commit() { asm volatile("cp.async.commit_group;"); }
__device__ __forceinline__ void cp_wait1()  { asm volatile("cp.async.wait_group 1;"); }

// fp16 mma, k=16, fp32 accumulate
__device__ __forceinline__ void mma16(float* c, uint32_t a0, uint32_t a1, uint32_t a2,
                                      uint32_t a3, uint32_t b0, uint32_t b1) {
    asm volatile(
        "mma.sync.aligned.m16n8k16.row.col.f32.f16.f16.f32 "
        "{%0,%1,%2,%3}, {%4,%5,%6,%7}, {%8,%9}, {%0,%1,%2,%3};"
        : "+f"(c[0]), "+f"(c[1]), "+f"(c[2]), "+f"(c[3])
        : "r"(a0), "r"(a1), "r"(a2), "r"(a3), "r"(b0), "r"(b1));
}
__device__ __forceinline__ void ldsm4(uint32_t* r, uint32_t addr) {
    asm volatile("ldmatrix.sync.aligned.m8n8.x4.shared.b16 {%0,%1,%2,%3}, [%4];"
                 : "=r"(r[0]), "=r"(r[1]), "=r"(r[2]), "=r"(r[3]) : "r"(addr));
}
__device__ __forceinline__ uint32_t pack_h2(float lo, float hi) {
    __half2 h = __floats2half2_rn(lo, hi);
    return *(uint32_t*)&h;
}

// ---------------- small kernels ----------------
__global__ void zero_cnt_kernel() { if (threadIdx.x < NE) g_cnt[threadIdx.x] = 0; }

// ===== merged pre-kernel: gate (+x->fp16) blocks THEN weight transpose blocks =====
// blocks [0, GATE_BLOCKS): gate; rest: 64x64 transpose+fp16 tiles.
#define GATE_BLOCKS 512
#define TILES_W1 ((FF / 64) * (DD / 64) * NE)   // 8192 per matrix
__global__ void pre_kernel(const float* __restrict__ x,
                           const float* __restrict__ gw, int T,
                           const float* __restrict__ w1, __half* __restrict__ d1,
                           const float* __restrict__ w3, __half* __restrict__ d3,
                           const float* __restrict__ w2, __half* __restrict__ d2) {
    __shared__ float t[64][65];

    if (blockIdx.x < GATE_BLOCKS) {
        // ---- gate path: one warp per token, fused x->fp16 ----
        int warp = (blockIdx.x * blockDim.x + threadIdx.x) >> 5;
        int lane = threadIdx.x & 31;
        if (warp >= T) return;
        const float2* xr2 = (const float2*)(x + (size_t)warp * DD);
        __half* xo = g_Xh + (size_t)warp * DD;
        float acc[NE];
#pragma unroll
        for (int e = 0; e < NE; e++) acc[e] = 0.f;
        for (int i = lane; i < DD / 2; i += 32) {
            float2 v = xr2[i];
            int d = 2 * i;
            const float* g0 = gw + (size_t)d * NE;
#pragma unroll
            for (int e = 0; e < NE; e++) acc[e] += v.x * g0[e] + v.y * g0[NE + e];
            *(uint32_t*)(xo + d) = pack_h2(v.x, v.y);
        }
#pragma unroll
        for (int e = 0; e < NE; e++)
#pragma unroll
            for (int off = 16; off > 0; off >>= 1)
                acc[e] += __shfl_xor_sync(0xffffffffu, acc[e], off);
        if (lane == 0) {
            int i0 = 0; float v0 = acc[0];
#pragma unroll
            for (int e = 1; e < NE; e++) if (acc[e] > v0) { v0 = acc[e]; i0 = e; }
            int i1 = -1; float v1 = -3.0e38f;
#pragma unroll
            for (int e = 0; e < NE; e++)
                if (e != i0 && acc[e] > v1) { v1 = acc[e]; i1 = e; }
            float tt = expf(v1 - v0);
            float w0 = 1.f / (1.f + tt);
            float w1s = tt / (1.f + tt);
            int s0 = atomicAdd(&g_cnt[i0], 1);
            g_tok[i0 * TMAX + s0] = warp; g_wt[i0 * TMAX + s0] = w0;
            int s1 = atomicAdd(&g_cnt[i1], 1);
            g_tok[i1 * TMAX + s1] = warp; g_wt[i1 * TMAX + s1] = w1s;
        }
        return;
    }

    // ---- transpose path ----
    int bid = blockIdx.x - GATE_BLOCKS;
    const float* src; __half* dst; int R, C;
    if (bid < TILES_W1)          { src = w1; dst = d1; R = DD; C = FF; }
    else if (bid < 2 * TILES_W1) { src = w3; dst = d3; R = DD; C = FF; bid -= TILES_W1; }
    else                         { src = w2; dst = d2; R = FF; C = DD; bid -= 2 * TILES_W1; }
    int tilesC = C / 64, tilesR = R / 64;
    int b   = bid / (tilesC * tilesR);
    int rem = bid % (tilesC * tilesR);
    int c0 = (rem % tilesC) * 64, r0 = (rem / tilesC) * 64;
    const float* s = src + (size_t)b * R * C;
    __half* d = dst + (size_t)b * R * C;
    int lane = threadIdx.x & 31, w = threadIdx.x >> 5;
#pragma unroll
    for (int i = 0; i < 8; i++) {
        int r = w * 8 + i;
        const float* srow = s + (size_t)(r0 + r) * C + c0;
        t[r][lane]      = srow[lane];
        t[r][lane + 32] = srow[lane + 32];
    }
    __syncthreads();
    int m  = lane & 15;
    int hs = lane >> 4;
#pragma unroll
    for (int it = 0; it < 4; it++) {
        int cl = it * 16 + w * 2 + hs;
        uint2 v;
        v.x = pack_h2(t[4 * m][cl],     t[4 * m + 1][cl]);
        v.y = pack_h2(t[4 * m + 2][cl], t[4 * m + 3][cl]);
        *(uint2*)(d + (size_t)(c0 + cl) * R + r0 + 4 * m) = v;
    }
}

// ======================= GEMM1: H = silu(X W1) * (X W3) * wgt =======================
// fp16, BK=64, block 128x64, 8 warps (4m x 2n), warp tile 32x32 dual.
// 2 stages x 36864B = 72KB -> 2 CTAs/SM. R10-proven loop ordering.
#define G_STAGE_B 36864
#define G_SMEM   (2 * G_STAGE_B)

__global__ void __launch_bounds__(256, 2)
gemm1_mma(const __half* __restrict__ Xh,
          const __half* __restrict__ w1t,
          const __half* __restrict__ w3t) {
    const int e    = blockIdx.z;
    const int cnt  = g_cnt[e];
    const int row0 = blockIdx.x * 128;   // m fast
    if (row0 >= cnt) return;
    const int n0   = blockIdx.y * 64;

    extern __shared__ char smc[];
    const uint32_t sbase = smem_u32(smc);

    const int tid  = threadIdx.x;
    const int lane = tid & 31;
    const int wm   = (tid >> 5) & 3;
    const int wn   = (tid >> 5) >> 2;
    const int gId  = lane >> 2;
    const int tId  = lane & 3;
    const int q    = lane >> 3;
    const int jr   = lane & 7;

    uint32_t aLd[2];
#pragma unroll
    for (int mi = 0; mi < 2; mi++)
        aLd[mi] = sbase + (uint32_t)((wm * 32 + mi * 16 + (q & 1) * 8 + jr) * 144)
                        + (uint32_t)((q >> 1) * 16);
    uint32_t b1Ld[2], b3Ld[2];
#pragma unroll
    for (int p = 0; p < 2; p++) {
        uint32_t nrow = (uint32_t)(wn * 32 + (p * 2 + (q >> 1)) * 8 + jr);
        b1Ld[p] = sbase + 18432u + nrow * 144u + (uint32_t)((q & 1) * 16);
        b3Ld[p] = b1Ld[p] + 9216u;
    }

    const __half* asrc[4]; uint32_t adst[4];
#pragma unroll
    for (int j = 0; j < 4; j++) {
        int c = tid + 256 * j;
        int row = c >> 3, kc = c & 7;
        int rr = row0 + row; if (rr >= cnt) rr = cnt - 1;
        int tok = g_tok[e * TMAX + rr];
        asrc[j] = Xh + (size_t)tok * DD + kc * 8;
        adst[j] = 144u * row + 16u * kc;
    }
    const __half* bsrc[4]; uint32_t bdst[4];
#pragma unroll
    for (int j = 0; j < 4; j++) {
        int c = tid + 256 * j;
        int mat = c >> 9, cc = c & 511;
        int n = cc >> 3, kc = cc & 7;
        const __half* w = mat ? w3t : w1t;
        bsrc[j] = w + (size_t)e * DD * FF + (size_t)(n0 + n) * DD + kc * 8;
        bdst[j] = 18432u + (uint32_t)mat * 9216u + 144u * n + 16u * kc;
    }

#define G1_ISSUE(KT, S) do {                                        \
        uint32_t so_ = sbase + (uint32_t)(S) * G_STAGE_B;           \
        int k0_ = (KT) * 64;                                        \
        _Pragma("unroll")                                           \
        for (int j = 0; j < 4; j++) cp16(so_ + adst[j], asrc[j] + k0_); \
        _Pragma("unroll")                                           \
        for (int j = 0; j < 4; j++) cp16(so_ + bdst[j], bsrc[j] + k0_); \
    } while (0)

    G1_ISSUE(0, 0); cp_commit();
    G1_ISSUE(1, 1); cp_commit();

    float acc1[2][4][4], acc3[2][4][4];
#pragma unroll
    for (int mi = 0; mi < 2; mi++)
#pragma unroll
        for (int ni = 0; ni < 4; ni++)
#pragma unroll
            for (int qq = 0; qq < 4; qq++) { acc1[mi][ni][qq] = 0.f; acc3[mi][ni][qq] = 0.f; }

    const int NKT = DD / 64;   // 16
    for (int kt = 0; kt < NKT; kt++) {
        cp_wait1();
        __syncthreads();
        const uint32_t stOff = (uint32_t)(kt & 1) * G_STAGE_B;

#pragma unroll
        for (int s = 0; s < 4; s++) {
            const uint32_t soff = stOff + (uint32_t)s * 32u;
            uint32_t a[2][4];
            ldsm4(a[0], aLd[0] + soff);
            ldsm4(a[1], aLd[1] + soff);
#pragma unroll
            for (int p = 0; p < 2; p++) {
                uint32_t B1r[4], B3r[4];
                ldsm4(B1r, b1Ld[p] + soff);
                ldsm4(B3r, b3Ld[p] + soff);
#pragma unroll
                for (int qq = 0; qq < 2; qq++) {
                    int ni = 2 * p + qq;
#pragma unroll
                    for (int mi = 0; mi < 2; mi++) {
                        mma16(acc1[mi][ni], a[mi][0], a[mi][1], a[mi][2], a[mi][3],
                              B1r[2 * qq], B1r[2 * qq + 1]);
                        mma16(acc3[mi][ni], a[mi][0], a[mi][1], a[mi][2], a[mi][3],
                              B3r[2 * qq], B3r[2 * qq + 1]);
                    }
                }
            }
        }
        __syncthreads();
        if (kt + 2 < NKT) { G1_ISSUE(kt + 2, kt & 1); }
        cp_commit();
    }

    // ---- epilogue: SwiGLU * gate weight -> g_H (fp16) ----
#pragma unroll
    for (int mi = 0; mi < 2; mi++) {
        int rbase = row0 + wm * 32 + mi * 16 + gId;
#pragma unroll
        for (int half = 0; half < 2; half++) {
            int r = rbase + half * 8;
            if (r < cnt) {
                float wgt = g_wt[e * TMAX + r];
                __half* hp = g_H + ((size_t)e * TMAX + r) * FF;
#pragma unroll
                for (int ni = 0; ni < 4; ni++) {
                    int col = n0 + wn * 32 + ni * 8 + tId * 2;
                    float h1a = acc1[mi][ni][half * 2 + 0];
                    float h1b = acc1[mi][ni][half * 2 + 1];
                    float h3a = acc3[mi][ni][half * 2 + 0];
                    float h3b = acc3[mi][ni][half * 2 + 1];
                    float oa = (h1a / (1.f + __expf(-h1a))) * h3a * wgt;
                    float ob = (h1b / (1.f + __expf(-h1b))) * h3b * wgt;
                    *(uint32_t*)(hp + col) = pack_h2(oa, ob);
                }
            }
        }
    }
}

// ======================= GEMM2: out[tok] += H W2 =======================
// fp16, BK=64, block 128x64 (better wave quantization: 1024 active CTAs vs 512),
// 8 warps (4m x 2n), warp tile 32x32, ldmatrix feeds.
// stage: A 18432B + B 9216B = 27648B, 2 stages = 55296B -> 2 CTAs/SM.
#define G2_STAGE_B 27648
#define G2_SMEM   (2 * G2_STAGE_B)

__global__ void __launch_bounds__(256, 2)
gemm2_mma(const __half* __restrict__ w2t, float* __restrict__ out) {
    const int e    = blockIdx.z;
    const int cnt  = g_cnt[e];
    const int row0 = blockIdx.x * 128;
    if (row0 >= cnt) return;
    const int n0   = blockIdx.y * 64;

    extern __shared__ char smc[];
    const uint32_t sbase = smem_u32(smc);

    const int tid  = threadIdx.x;
    const int lane = tid & 31;
    const int wm   = (tid >> 5) & 3;
    const int wn   = (tid >> 5) >> 2;
    const int gId  = lane >> 2;
    const int tId  = lane & 3;
    const int q    = lane >> 3;
    const int jr   = lane & 7;

    uint32_t aLd[2];
#pragma unroll
    for (int mi = 0; mi < 2; mi++)
        aLd[mi] = sbase + (uint32_t)((wm * 32 + mi * 16 + (q & 1) * 8 + jr) * 144)
                        + (uint32_t)((q >> 1) * 16);
    uint32_t bLd[2];
#pragma unroll
    for (int p = 0; p < 2; p++) {
        uint32_t nrow = (uint32_t)(wn * 32 + (p * 2 + (q >> 1)) * 8 + jr);
        bLd[p] = sbase + 18432u + nrow * 144u + (uint32_t)((q & 1) * 16);
    }

    // A: 128 rows x 8 chunks = 1024 -> 4/thread;  B: 64 rows x 8 chunks = 512 -> 2/thread
    const __half* asrc[4]; uint32_t adst[4];
#pragma unroll
    for (int j = 0; j < 4; j++) {
        int c = tid + 256 * j;
        int row = c >> 3, kc = c & 7;
        int rr = row0 + row; if (rr >= cnt) rr = cnt - 1;
        asrc[j] = g_H + ((size_t)e * TMAX + rr) * FF + kc * 8;
        adst[j] = 144u * row + 16u * kc;
    }
    const __half* bsrc[2]; uint32_t bdst[2];
#pragma unroll
    for (int j = 0; j < 2; j++) {
        int c = tid + 256 * j;
        int n = c >> 3, kc = c & 7;
        bsrc[j] = w2t + (size_t)e * FF * DD + (size_t)(n0 + n) * FF + kc * 8;
        bdst[j] = 18432u + 144u * n + 16u * kc;
    }

#define G2_ISSUE(KT, S) do {                                        \
        uint32_t so_ = sbase + (uint32_t)(S) * G2_STAGE_B;          \
        int k0_ = (KT) * 64;                                        \
        _Pragma("unroll")                                           \
        for (int j = 0; j < 4; j++) cp16(so_ + adst[j], asrc[j] + k0_); \
        _Pragma("unroll")                                           \
        for (int j = 0; j < 2; j++) cp16(so_ + bdst[j], bsrc[j] + k0_); \
    } while (0)

    G2_ISSUE(0, 0); cp_commit();
    G2_ISSUE(1, 1); cp_commit();

    float acc[2][4][4];
#pragma unroll
    for (int mi = 0; mi < 2; mi++)
#pragma unroll
        for (int ni = 0; ni < 4; ni++)
#pragma unroll
            for (int qq = 0; qq < 4; qq++) acc[mi][ni][qq] = 0.f;

    const int NKT = FF / 64;   // 64
    for (int kt = 0; kt < NKT; kt++) {
        cp_wait1();
        __syncthreads();
        const uint32_t stOff = (uint32_t)(kt & 1) * G2_STAGE_B;

#pragma unroll
        for (int s = 0; s < 4; s++) {
            const uint32_t soff = stOff + (uint32_t)s * 32u;
            uint32_t a[2][4];
            ldsm4(a[0], aLd[0] + soff);
            ldsm4(a[1], aLd[1] + soff);
#pragma unroll
            for (int p = 0; p < 2; p++) {
                uint32_t Br[4];
                ldsm4(Br, bLd[p] + soff);
#pragma unroll
                for (int qq = 0; qq < 2; qq++) {
                    int ni = 2 * p + qq;
#pragma unroll
                    for (int mi = 0; mi < 2; mi++)
                        mma16(acc[mi][ni], a[mi][0], a[mi][1], a[mi][2], a[mi][3],
                              Br[2 * qq], Br[2 * qq + 1]);
                }
            }
        }
        __syncthreads();
        if (kt + 2 < NKT) { G2_ISSUE(kt + 2, kt & 1); }
        cp_commit();
    }

    // ---- epilogue: atomic scatter into out (fp32) ----
#pragma unroll
    for (int mi = 0; mi < 2; mi++) {
        int rbase = row0 + wm * 32 + mi * 16 + gId;
#pragma unroll
        for (int half = 0; half < 2; half++) {
            int r = rbase + half * 8;
            if (r < cnt) {
                int tok = g_tok[e * TMAX + r];
                float* op = out + (size_t)tok * DD;
#pragma unroll
                for (int ni = 0; ni < 4; ni++) {
                    int col = n0 + wn * 32 + ni * 8 + tId * 2;
                    atomicAdd(&op[col],     acc[mi][ni][half * 2 + 0]);
                    atomicAdd(&op[col + 1], acc[mi][ni][half * 2 + 1]);
                }
            }
        }
    }
}

// ---------------- host ----------------
extern "C" void kernel_launch(void* const* d_in, const int* in_sizes, int n_in,
                              void* d_out, int out_size) {
    const float* x  = (const float*)d_in[0];
    const float* gw = (const float*)d_in[1];
    const float* w1 = (const float*)d_in[2];
    const float* w2 = (const float*)d_in[3];
    const float* w3 = (const float*)d_in[4];
    float* out = (float*)d_out;
    int T = in_sizes[0] / DD;   // 4096

    void *pW1t, *pW2t, *pW3t, *pXh;
    cudaGetSymbolAddress(&pXh,  g_Xh);
    cudaGetSymbolAddress(&pW1t, g_w1t);
    cudaGetSymbolAddress(&pW2t, g_w2t);
    cudaGetSymbolAddress(&pW3t, g_w3t);

    cudaFuncSetAttribute(gemm1_mma, cudaFuncAttributeMaxDynamicSharedMemorySize, G_SMEM);
    cudaFuncSetAttribute(gemm2_mma, cudaFuncAttributeMaxDynamicSharedMemorySize, G2_SMEM);

    cudaMemsetAsync(out, 0, (size_t)out_size * sizeof(float), 0);
    zero_cnt_kernel<<<1, 32>>>();

    // merged gate + weight transpose: gate latency hides under DRAM-bound transpose
    pre_kernel<<<GATE_BLOCKS + 3 * TILES_W1, 256>>>(
        x, gw, T,
        w1, (__half*)pW1t, w3, (__half*)pW3t, w2, (__half*)pW2t);

    dim3 g1(TMAX / 128, FF / 64, NE);
    gemm1_mma<<<g1, 256, G_SMEM>>>((const __half*)pXh, (const __half*)pW1t, (const __half*)pW3t);

    dim3 g2(TMAX / 128, DD / 64, NE);
    gemm2_mma<<<g2, 256, G2_SMEM>>>((const __half*)pW2t, out);
}

// round 16
// speedup vs baseline: 1.0686x; 1.0686x over previous
#include <cuda_runtime.h>
#include <cuda_fp16.h>
#include <cstdint>
#include <math.h>

#define NE   8
#define DD   1024
#define FF   4096
#define TMAX 4096

// ---------------- device scratch ----------------
__device__ int    g_cnt[NE];
__device__ int    g_tok[NE * TMAX];
__device__ float  g_wt [NE * TMAX];
__device__ __half g_Xh [(size_t)TMAX * DD];          // fp16 x (k-major)
__device__ __half g_w1t[(size_t)NE * DD * FF];       // fp16 w1^T : [E][F][D] (n-major)
__device__ __half g_w3t[(size_t)NE * DD * FF];       // fp16 w3^T : [E][F][D]
__device__ __half g_w2t[(size_t)NE * FF * DD];       // fp16 w2^T : [E][D][F]
__device__ __half g_H  [(size_t)NE * TMAX * FF];     // fp16 SwiGLU acts (k-major)

// ---------------- helpers ----------------
__device__ __forceinline__ uint32_t smem_u32(const void* p) {
    uint32_t a;
    asm("{ .reg .u64 t; cvta.to.shared.u64 t, %1; cvt.u32.u64 %0, t; }" : "=r"(a) : "l"(p));
    return a;
}
__device__ __forceinline__ void cp16(uint32_t dst, const void* src) {
    asm volatile("cp.async.cg.shared.global [%0], [%1], 16;" :: "r"(dst), "l"(src));
}
__device__ __forceinline__ void cp_commit() { asm volatile("cp.async.commit_group;"); }
__device__ __forceinline__ void cp_wait1()  { asm volatile("cp.async.wait_group 1;"); }

// fp16 mma, k=16, fp32 accumulate
__device__ __forceinline__ void mma16(float* c, uint32_t a0, uint32_t a1, uint32_t a2,
                                      uint32_t a3, uint32_t b0, uint32_t b1) {
    asm volatile(
        "mma.sync.aligned.m16n8k16.row.col.f32.f16.f16.f32 "
        "{%0,%1,%2,%3}, {%4,%5,%6,%7}, {%8,%9}, {%0,%1,%2,%3};"
        : "+f"(c[0]), "+f"(c[1]), "+f"(c[2]), "+f"(c[3])
        : "r"(a0), "r"(a1), "r"(a2), "r"(a3), "r"(b0), "r"(b1));
}
__device__ __forceinline__ void ldsm4(uint32_t* r, uint32_t addr) {
    asm volatile("ldmatrix.sync.aligned.m8n8.x4.shared.b16 {%0,%1,%2,%3}, [%4];"
                 : "=r"(r[0]), "=r"(r[1]), "=r"(r[2]), "=r"(r[3]) : "r"(addr));
}
__device__ __forceinline__ uint32_t pack_h2(float lo, float hi) {
    __half2 h = __floats2half2_rn(lo, hi);
    return *(uint32_t*)&h;
}

// ---------------- small kernels ----------------
__global__ void zero_cnt_kernel() { if (threadIdx.x < NE) g_cnt[threadIdx.x] = 0; }

// ===== merged pre-kernel: gate (+x->fp16) blocks THEN weight transpose blocks =====
#define GATE_BLOCKS 512
#define TILES_W1 ((FF / 64) * (DD / 64) * NE)   // 8192 per matrix
__global__ void pre_kernel(const float* __restrict__ x,
                           const float* __restrict__ gw, int T,
                           const float* __restrict__ w1, __half* __restrict__ d1,
                           const float* __restrict__ w3, __half* __restrict__ d3,
                           const float* __restrict__ w2, __half* __restrict__ d2) {
    __shared__ float t[64][65];

    if (blockIdx.x < GATE_BLOCKS) {
        // ---- gate path: one warp per token, fused x->fp16 ----
        int warp = (blockIdx.x * blockDim.x + threadIdx.x) >> 5;
        int lane = threadIdx.x & 31;
        if (warp >= T) return;
        const float2* xr2 = (const float2*)(x + (size_t)warp * DD);
        __half* xo = g_Xh + (size_t)warp * DD;
        float acc[NE];
#pragma unroll
        for (int e = 0; e < NE; e++) acc[e] = 0.f;
        for (int i = lane; i < DD / 2; i += 32) {
            float2 v = xr2[i];
            int d = 2 * i;
            const float* g0 = gw + (size_t)d * NE;
#pragma unroll
            for (int e = 0; e < NE; e++) acc[e] += v.x * g0[e] + v.y * g0[NE + e];
            *(uint32_t*)(xo + d) = pack_h2(v.x, v.y);
        }
#pragma unroll
        for (int e = 0; e < NE; e++)
#pragma unroll
            for (int off = 16; off > 0; off >>= 1)
                acc[e] += __shfl_xor_sync(0xffffffffu, acc[e], off);
        if (lane == 0) {
            int i0 = 0; float v0 = acc[0];
#pragma unroll
            for (int e = 1; e < NE; e++) if (acc[e] > v0) { v0 = acc[e]; i0 = e; }
            int i1 = -1; float v1 = -3.0e38f;
#pragma unroll
            for (int e = 0; e < NE; e++)
                if (e != i0 && acc[e] > v1) { v1 = acc[e]; i1 = e; }
            float tt = expf(v1 - v0);
            float w0 = 1.f / (1.f + tt);
            float w1s = tt / (1.f + tt);
            int s0 = atomicAdd(&g_cnt[i0], 1);
            g_tok[i0 * TMAX + s0] = warp; g_wt[i0 * TMAX + s0] = w0;
            int s1 = atomicAdd(&g_cnt[i1], 1);
            g_tok[i1 * TMAX + s1] = warp; g_wt[i1 * TMAX + s1] = w1s;
        }
        return;
    }

    // ---- transpose path ----
    int bid = blockIdx.x - GATE_BLOCKS;
    const float* src; __half* dst; int R, C;
    if (bid < TILES_W1)          { src = w1; dst = d1; R = DD; C = FF; }
    else if (bid < 2 * TILES_W1) { src = w3; dst = d3; R = DD; C = FF; bid -= TILES_W1; }
    else                         { src = w2; dst = d2; R = FF; C = DD; bid -= 2 * TILES_W1; }
    int tilesC = C / 64, tilesR = R / 64;
    int b   = bid / (tilesC * tilesR);
    int rem = bid % (tilesC * tilesR);
    int c0 = (rem % tilesC) * 64, r0 = (rem / tilesC) * 64;
    const float* s = src + (size_t)b * R * C;
    __half* d = dst + (size_t)b * R * C;
    int lane = threadIdx.x & 31, w = threadIdx.x >> 5;
#pragma unroll
    for (int i = 0; i < 8; i++) {
        int r = w * 8 + i;
        const float* srow = s + (size_t)(r0 + r) * C + c0;
        t[r][lane]      = srow[lane];
        t[r][lane + 32] = srow[lane + 32];
    }
    __syncthreads();
    int m  = lane & 15;
    int hs = lane >> 4;
#pragma unroll
    for (int it = 0; it < 4; it++) {
        int cl = it * 16 + w * 2 + hs;
        uint2 v;
        v.x = pack_h2(t[4 * m][cl],     t[4 * m + 1][cl]);
        v.y = pack_h2(t[4 * m + 2][cl], t[4 * m + 3][cl]);
        *(uint2*)(d + (size_t)(c0 + cl) * R + r0 + 4 * m) = v;
    }
}

// ======================= GEMM1: H = silu(X W1) * (X W3) * wgt =======================
// fp16, BK=64, block 128x64, 8 warps (4m x 2n), warp tile 32x32 dual.
// 2 stages x 36864B = 72KB -> 2 CTAs/SM. R10-proven loop ordering.
#define G_STAGE_B 36864
#define G_SMEM   (2 * G_STAGE_B)

__global__ void __launch_bounds__(256, 2)
gemm1_mma(const __half* __restrict__ Xh,
          const __half* __restrict__ w1t,
          const __half* __restrict__ w3t) {
    const int e    = blockIdx.z;
    const int cnt  = g_cnt[e];
    const int row0 = blockIdx.x * 128;   // m fast
    if (row0 >= cnt) return;
    const int n0   = blockIdx.y * 64;

    extern __shared__ char smc[];
    const uint32_t sbase = smem_u32(smc);

    const int tid  = threadIdx.x;
    const int lane = tid & 31;
    const int wm   = (tid >> 5) & 3;
    const int wn   = (tid >> 5) >> 2;
    const int gId  = lane >> 2;
    const int tId  = lane & 3;
    const int q    = lane >> 3;
    const int jr   = lane & 7;

    uint32_t aLd[2];
#pragma unroll
    for (int mi = 0; mi < 2; mi++)
        aLd[mi] = sbase + (uint32_t)((wm * 32 + mi * 16 + (q & 1) * 8 + jr) * 144)
                        + (uint32_t)((q >> 1) * 16);
    uint32_t b1Ld[2], b3Ld[2];
#pragma unroll
    for (int p = 0; p < 2; p++) {
        uint32_t nrow = (uint32_t)(wn * 32 + (p * 2 + (q >> 1)) * 8 + jr);
        b1Ld[p] = sbase + 18432u + nrow * 144u + (uint32_t)((q & 1) * 16);
        b3Ld[p] = b1Ld[p] + 9216u;
    }

    const __half* asrc[4]; uint32_t adst[4];
#pragma unroll
    for (int j = 0; j < 4; j++) {
        int c = tid + 256 * j;
        int row = c >> 3, kc = c & 7;
        int rr = row0 + row; if (rr >= cnt) rr = cnt - 1;
        int tok = g_tok[e * TMAX + rr];
        asrc[j] = Xh + (size_t)tok * DD + kc * 8;
        adst[j] = 144u * row + 16u * kc;
    }
    const __half* bsrc[4]; uint32_t bdst[4];
#pragma unroll
    for (int j = 0; j < 4; j++) {
        int c = tid + 256 * j;
        int mat = c >> 9, cc = c & 511;
        int n = cc >> 3, kc = cc & 7;
        const __half* w = mat ? w3t : w1t;
        bsrc[j] = w + (size_t)e * DD * FF + (size_t)(n0 + n) * DD + kc * 8;
        bdst[j] = 18432u + (uint32_t)mat * 9216u + 144u * n + 16u * kc;
    }

#define G1_ISSUE(KT, S) do {                                        \
        uint32_t so_ = sbase + (uint32_t)(S) * G_STAGE_B;           \
        int k0_ = (KT) * 64;                                        \
        _Pragma("unroll")                                           \
        for (int j = 0; j < 4; j++) cp16(so_ + adst[j], asrc[j] + k0_); \
        _Pragma("unroll")                                           \
        for (int j = 0; j < 4; j++) cp16(so_ + bdst[j], bsrc[j] + k0_); \
    } while (0)

    G1_ISSUE(0, 0); cp_commit();
    G1_ISSUE(1, 1); cp_commit();

    float acc1[2][4][4], acc3[2][4][4];
#pragma unroll
    for (int mi = 0; mi < 2; mi++)
#pragma unroll
        for (int ni = 0; ni < 4; ni++)
#pragma unroll
            for (int qq = 0; qq < 4; qq++) { acc1[mi][ni][qq] = 0.f; acc3[mi][ni][qq] = 0.f; }

    const int NKT = DD / 64;   // 16
    for (int kt = 0; kt < NKT; kt++) {
        cp_wait1();
        __syncthreads();
        const uint32_t stOff = (uint32_t)(kt & 1) * G_STAGE_B;

#pragma unroll
        for (int s = 0; s < 4; s++) {
            const uint32_t soff = stOff + (uint32_t)s * 32u;
            uint32_t a[2][4];
            ldsm4(a[0], aLd[0] + soff);
            ldsm4(a[1], aLd[1] + soff);
#pragma unroll
            for (int p = 0; p < 2; p++) {
                uint32_t B1r[4], B3r[4];
                ldsm4(B1r, b1Ld[p] + soff);
                ldsm4(B3r, b3Ld[p] + soff);
#pragma unroll
                for (int qq = 0; qq < 2; qq++) {
                    int ni = 2 * p + qq;
#pragma unroll
                    for (int mi = 0; mi < 2; mi++) {
                        mma16(acc1[mi][ni], a[mi][0], a[mi][1], a[mi][2], a[mi][3],
                              B1r[2 * qq], B1r[2 * qq + 1]);
                        mma16(acc3[mi][ni], a[mi][0], a[mi][1], a[mi][2], a[mi][3],
                              B3r[2 * qq], B3r[2 * qq + 1]);
                    }
                }
            }
        }
        __syncthreads();
        if (kt + 2 < NKT) { G1_ISSUE(kt + 2, kt & 1); }
        cp_commit();
    }

    // ---- epilogue: SwiGLU * gate weight -> g_H (fp16) ----
#pragma unroll
    for (int mi = 0; mi < 2; mi++) {
        int rbase = row0 + wm * 32 + mi * 16 + gId;
#pragma unroll
        for (int half = 0; half < 2; half++) {
            int r = rbase + half * 8;
            if (r < cnt) {
                float wgt = g_wt[e * TMAX + r];
                __half* hp = g_H + ((size_t)e * TMAX + r) * FF;
#pragma unroll
                for (int ni = 0; ni < 4; ni++) {
                    int col = n0 + wn * 32 + ni * 8 + tId * 2;
                    float h1a = acc1[mi][ni][half * 2 + 0];
                    float h1b = acc1[mi][ni][half * 2 + 1];
                    float h3a = acc3[mi][ni][half * 2 + 0];
                    float h3b = acc3[mi][ni][half * 2 + 1];
                    float oa = (h1a / (1.f + __expf(-h1a))) * h3a * wgt;
                    float ob = (h1b / (1.f + __expf(-h1b))) * h3b * wgt;
                    *(uint32_t*)(hp + col) = pack_h2(oa, ob);
                }
            }
        }
    }
}

// ======================= GEMM2: out[tok] += H W2 =======================
// fp16, BK=64, block 128x128, warp tile 32x64, ldmatrix feeds.
// 2 stages, R10-proven loop ordering (R15's 128x64 tile regressed; reverted).
__global__ void __launch_bounds__(256, 2)
gemm2_mma(const __half* __restrict__ w2t, float* __restrict__ out) {
    const int e    = blockIdx.z;
    const int cnt  = g_cnt[e];
    const int row0 = blockIdx.x * 128;
    if (row0 >= cnt) return;
    const int n0   = blockIdx.y * 128;

    extern __shared__ char smc[];
    const uint32_t sbase = smem_u32(smc);

    const int tid  = threadIdx.x;
    const int lane = tid & 31;
    const int wm   = (tid >> 5) & 3;
    const int wn   = (tid >> 5) >> 2;
    const int gId  = lane >> 2;
    const int tId  = lane & 3;
    const int q    = lane >> 3;
    const int jr   = lane & 7;

    uint32_t aLd[2];
#pragma unroll
    for (int mi = 0; mi < 2; mi++)
        aLd[mi] = sbase + (uint32_t)((wm * 32 + mi * 16 + (q & 1) * 8 + jr) * 144)
                        + (uint32_t)((q >> 1) * 16);
    uint32_t bLd[4];
#pragma unroll
    for (int p = 0; p < 4; p++) {
        uint32_t nrow = (uint32_t)(wn * 64 + (p * 2 + (q >> 1)) * 8 + jr);
        bLd[p] = sbase + 18432u + nrow * 144u + (uint32_t)((q & 1) * 16);
    }

    const __half* asrc[4]; uint32_t adst[4];
#pragma unroll
    for (int j = 0; j < 4; j++) {
        int c = tid + 256 * j;
        int row = c >> 3, kc = c & 7;
        int rr = row0 + row; if (rr >= cnt) rr = cnt - 1;
        asrc[j] = g_H + ((size_t)e * TMAX + rr) * FF + kc * 8;
        adst[j] = 144u * row + 16u * kc;
    }
    const __half* bsrc[4]; uint32_t bdst[4];
#pragma unroll
    for (int j = 0; j < 4; j++) {
        int c = tid + 256 * j;
        int n = c >> 3, kc = c & 7;
        bsrc[j] = w2t + (size_t)e * FF * DD + (size_t)(n0 + n) * FF + kc * 8;
        bdst[j] = 18432u + 144u * n + 16u * kc;
    }

#define G2_ISSUE(KT, S) do {                                        \
        uint32_t so_ = sbase + (uint32_t)(S) * G_STAGE_B;           \
        int k0_ = (KT) * 64;                                        \
        _Pragma("unroll")                                           \
        for (int j = 0; j < 4; j++) cp16(so_ + adst[j], asrc[j] + k0_); \
        _Pragma("unroll")                                           \
        for (int j = 0; j < 4; j++) cp16(so_ + bdst[j], bsrc[j] + k0_); \
    } while (0)

    G2_ISSUE(0, 0); cp_commit();
    G2_ISSUE(1, 1); cp_commit();

    float acc[2][8][4];
#pragma unroll
    for (int mi = 0; mi < 2; mi++)
#pragma unroll
        for (int ni = 0; ni < 8; ni++)
#pragma unroll
            for (int qq = 0; qq < 4; qq++) acc[mi][ni][qq] = 0.f;

    const int NKT = FF / 64;   // 64
    for (int kt = 0; kt < NKT; kt++) {
        cp_wait1();
        __syncthreads();
        const uint32_t stOff = (uint32_t)(kt & 1) * G_STAGE_B;

#pragma unroll
        for (int s = 0; s < 4; s++) {
            const uint32_t soff = stOff + (uint32_t)s * 32u;
            uint32_t a[2][4];
            ldsm4(a[0], aLd[0] + soff);
            ldsm4(a[1], aLd[1] + soff);
#pragma unroll
            for (int p = 0; p < 4; p++) {
                uint32_t Br[4];
                ldsm4(Br, bLd[p] + soff);
#pragma unroll
                for (int qq = 0; qq < 2; qq++) {
                    int ni = 2 * p + qq;
#pragma unroll
                    for (int mi = 0; mi < 2; mi++)
                        mma16(acc[mi][ni], a[mi][0], a[mi][1], a[mi][2], a[mi][3],
                              Br[2 * qq], Br[2 * qq + 1]);
                }
            }
        }
        __syncthreads();
        if (kt + 2 < NKT) { G2_ISSUE(kt + 2, kt & 1); }
        cp_commit();
    }

    // ---- epilogue: atomic scatter into out (fp32) ----
#pragma unroll
    for (int mi = 0; mi < 2; mi++) {
        int rbase = row0 + wm * 32 + mi * 16 + gId;
#pragma unroll
        for (int half = 0; half < 2; half++) {
            int r = rbase + half * 8;
            if (r < cnt) {
                int tok = g_tok[e * TMAX + r];
                float* op = out + (size_t)tok * DD;
#pragma unroll
                for (int ni = 0; ni < 8; ni++) {
                    int col = n0 + wn * 64 + ni * 8 + tId * 2;
                    atomicAdd(&op[col],     acc[mi][ni][half * 2 + 0]);
                    atomicAdd(&op[col + 1], acc[mi][ni][half * 2 + 1]);
                }
            }
        }
    }
}

// ---------------- host ----------------
extern "C" void kernel_launch(void* const* d_in, const int* in_sizes, int n_in,
                              void* d_out, int out_size) {
    const float* x  = (const float*)d_in[0];
    const float* gw = (const float*)d_in[1];
    const float* w1 = (const float*)d_in[2];
    const float* w2 = (const float*)d_in[3];
    const float* w3 = (const float*)d_in[4];
    float* out = (float*)d_out;
    int T = in_sizes[0] / DD;   // 4096

    void *pW1t, *pW2t, *pW3t, *pXh;
    cudaGetSymbolAddress(&pXh,  g_Xh);
    cudaGetSymbolAddress(&pW1t, g_w1t);
    cudaGetSymbolAddress(&pW2t, g_w2t);
    cudaGetSymbolAddress(&pW3t, g_w3t);

    cudaFuncSetAttribute(gemm1_mma, cudaFuncAttributeMaxDynamicSharedMemorySize, G_SMEM);
    cudaFuncSetAttribute(gemm2_mma, cudaFuncAttributeMaxDynamicSharedMemorySize, G_SMEM);

    cudaMemsetAsync(out, 0, (size_t)out_size * sizeof(float), 0);
    zero_cnt_kernel<<<1, 32>>>();

    // merged gate + weight transpose (measured ~-40us vs serial launches)
    pre_kernel<<<GATE_BLOCKS + 3 * TILES_W1, 256>>>(
        x, gw, T,
        w1, (__half*)pW1t, w3, (__half*)pW3t, w2, (__half*)pW2t);

    dim3 g1(TMAX / 128, FF / 64, NE);
    gemm1_mma<<<g1, 256, G_SMEM>>>((const __half*)pXh, (const __half*)pW1t, (const __half*)pW3t);

    dim3 g2(TMAX / 128, DD / 128, NE);
    gemm2_mma<<<g2, 256, G_SMEM>>>((const __half*)pW2t, out);
}